// round 2
// baseline (speedup 1.0000x reference)
#include <cuda_runtime.h>
#include <math.h>

// Problem constants
#define NROWS 8192
#define DIM   512

// Scratch (device globals — no allocation allowed)
__device__ float g_w2[DIM];         // w2 = W @ a2   (row-wise dot, contraction over output dim)
__device__ float g_s2[NROWS];       // s2 = X @ w2
__device__ float g_p[NROWS];        // softmax(s2)
__device__ float g_up[128 * DIM];   // partial u = p @ X over 128 row-chunks
__device__ float g_u[DIM];          // u
__device__ float g_v[DIM];          // v = u @ W

// K1: w2[k] = dot(W[k,:], a2).  64 blocks x 256 threads, warp per row.
__global__ void k1_w2(const float* __restrict__ W,
                      const float* __restrict__ av) {
    const int warp = threadIdx.x >> 5, lane = threadIdx.x & 31;
    const int k = blockIdx.x * 8 + warp;             // 0..511
    const float4* Wr = (const float4*)(W + (size_t)k * DIM);
    const float4* A2 = (const float4*)(av + DIM);    // a2 = av[512:1024]
    float acc = 0.f;
    #pragma unroll
    for (int j = lane; j < 128; j += 32) {
        float4 w = Wr[j];
        float4 a = A2[j];
        acc = fmaf(w.x, a.x, acc);
        acc = fmaf(w.y, a.y, acc);
        acc = fmaf(w.z, a.z, acc);
        acc = fmaf(w.w, a.w, acc);
    }
    #pragma unroll
    for (int off = 16; off > 0; off >>= 1)
        acc += __shfl_down_sync(0xffffffffu, acc, off);
    if (lane == 0) g_w2[k] = acc;
}

// K2: s2[r] = dot(X[r,:], w2). 1024 blocks x 256 threads (warp per row, 8 rows/block).
__global__ void k2_s2(const float* __restrict__ X) {
    __shared__ float w2s[DIM];
    const int t = threadIdx.x;
    #pragma unroll
    for (int j = t; j < DIM; j += 256) w2s[j] = g_w2[j];
    __syncthreads();

    const int warp = t >> 5, lane = t & 31;
    const int r = blockIdx.x * 8 + warp;
    const float4* X4 = (const float4*)X;
    const float4* W4 = (const float4*)w2s;
    float acc = 0.f;
    #pragma unroll
    for (int j = lane; j < 128; j += 32) {
        float4 x = X4[r * 128 + j];
        float4 w = W4[j];
        acc = fmaf(x.x, w.x, acc);
        acc = fmaf(x.y, w.y, acc);
        acc = fmaf(x.z, w.z, acc);
        acc = fmaf(x.w, w.w, acc);
    }
    #pragma unroll
    for (int off = 16; off > 0; off >>= 1)
        acc += __shfl_down_sync(0xffffffffu, acc, off);
    if (lane == 0) g_s2[r] = acc;
}

// K3: softmax over 8192 values. 1 block, 1024 threads, 8 elems each.
__global__ void k3_softmax() {
    const int t = threadIdx.x;
    __shared__ float red[1024];
    float vals[8];
    float m = -INFINITY;
    #pragma unroll
    for (int j = 0; j < 8; j++) {
        vals[j] = g_s2[t + 1024 * j];
        m = fmaxf(m, vals[j]);
    }
    red[t] = m;
    __syncthreads();
    #pragma unroll
    for (int s = 512; s > 0; s >>= 1) {
        if (t < s) red[t] = fmaxf(red[t], red[t + s]);
        __syncthreads();
    }
    const float mx = red[0];
    __syncthreads();
    float lsum = 0.f;
    #pragma unroll
    for (int j = 0; j < 8; j++) {
        vals[j] = __expf(vals[j] - mx);
        lsum += vals[j];
    }
    red[t] = lsum;
    __syncthreads();
    #pragma unroll
    for (int s = 512; s > 0; s >>= 1) {
        if (t < s) red[t] += red[t + s];
        __syncthreads();
    }
    const float inv = 1.f / red[0];
    #pragma unroll
    for (int j = 0; j < 8; j++)
        g_p[t + 1024 * j] = vals[j] * inv;
}

// K4: u partials. 128 blocks x 256 threads; block b handles 64 rows.
// thread t accumulates columns t and t+256.
__global__ void k4_u_partial(const float* __restrict__ X) {
    const int b = blockIdx.x, t = threadIdx.x;
    const int r0 = b * 64;
    float acc0 = 0.f, acc1 = 0.f;
    #pragma unroll 4
    for (int i = 0; i < 64; i++) {
        const int r = r0 + i;
        const float pi = __ldg(&g_p[r]);
        const float* xr = X + (size_t)r * DIM;
        acc0 = fmaf(pi, xr[t], acc0);
        acc1 = fmaf(pi, xr[t + 256], acc1);
    }
    g_up[b * DIM + t] = acc0;
    g_up[b * DIM + t + 256] = acc1;
}

// K5a: reduce 128 u partials. 4 blocks x 128 threads.
__global__ void k5a_u_reduce() {
    const int d = blockIdx.x * 128 + threadIdx.x;
    float acc = 0.f;
    #pragma unroll 8
    for (int b = 0; b < 128; b++) acc += g_up[b * DIM + d];
    g_u[d] = acc;
}

// K5b: v[d] = sum_k u[k] * W[k,d]. 8 blocks x 64 threads, 4 accumulation chains.
__global__ void k5b_v(const float* __restrict__ W) {
    __shared__ float us[DIM];
    const int t = threadIdx.x;
    #pragma unroll
    for (int j = t; j < DIM; j += 64) us[j] = g_u[j];
    __syncthreads();
    const int d = blockIdx.x * 64 + t;
    float a0 = 0.f, a1 = 0.f, a2 = 0.f, a3 = 0.f;
    #pragma unroll 4
    for (int k = 0; k < DIM; k += 4) {
        a0 = fmaf(us[k + 0], W[(k + 0) * DIM + d], a0);
        a1 = fmaf(us[k + 1], W[(k + 1) * DIM + d], a1);
        a2 = fmaf(us[k + 2], W[(k + 2) * DIM + d], a2);
        a3 = fmaf(us[k + 3], W[(k + 3) * DIM + d], a3);
    }
    g_v[d] = (a0 + a1) + (a2 + a3);
}

// K6: broadcast v into every output row. float4 stores.
__global__ void k6_broadcast(float4* __restrict__ out4) {
    const unsigned g = blockIdx.x * 256u + threadIdx.x;   // 0 .. 1M-1
    const float4* v4 = (const float4*)g_v;
    out4[g] = __ldg(&v4[g & 127u]);
}

extern "C" void kernel_launch(void* const* d_in, const int* in_sizes, int n_in,
                              void* d_out, int out_size) {
    const float* X  = (const float*)d_in[0];   // node_features [8192,512]
    const float* W  = (const float*)d_in[1];   // weight_matrix [512,512]
    const float* av = (const float*)d_in[2];   // attention_vector [1024,1]
    float* out = (float*)d_out;                // [8192,512]

    k1_w2<<<64, 256>>>(W, av);
    k2_s2<<<NROWS / 8, 256>>>(X);
    k3_softmax<<<1, 1024>>>();
    k4_u_partial<<<128, 256>>>(X);
    k5a_u_reduce<<<4, 128>>>();
    k5b_v<<<8, 64>>>(W);
    k6_broadcast<<<(NROWS * DIM / 4) / 256, 256>>>((float4*)out);
}

// round 3
// speedup vs baseline: 1.0615x; 1.0615x over previous
#include <cuda_runtime.h>
#include <math.h>

#define NROWS 8192
#define DIM   512

// Scratch (device globals — no allocation allowed)
__device__ float g_w2[DIM];         // w2 = W @ a2
__device__ float g_s2[NROWS];       // s2 = X @ w2
__device__ float g_up[256 * DIM];   // partial u = p @ X over 256 row-chunks
__device__ float g_v[DIM];          // v = (p @ X) @ W

__device__ __forceinline__ float warpMax(float v) {
    #pragma unroll
    for (int o = 16; o; o >>= 1) v = fmaxf(v, __shfl_xor_sync(0xffffffffu, v, o));
    return v;
}
__device__ __forceinline__ float warpSum(float v) {
    #pragma unroll
    for (int o = 16; o; o >>= 1) v += __shfl_xor_sync(0xffffffffu, v, o);
    return v;
}

// K1: w2[k] = dot(W[k,:], a2).  64 blocks x 256 threads, warp per row.
__global__ __launch_bounds__(256) void k1_w2(const float* __restrict__ W,
                                             const float* __restrict__ av) {
    const int warp = threadIdx.x >> 5, lane = threadIdx.x & 31;
    const int k = blockIdx.x * 8 + warp;
    const float4* Wr = (const float4*)(W + (size_t)k * DIM);
    const float4* A2 = (const float4*)(av + DIM);    // a2 = av[512:1024]
    float acc = 0.f;
    #pragma unroll
    for (int j = lane; j < 128; j += 32) {
        float4 w = Wr[j];
        float4 a = A2[j];
        acc = fmaf(w.x, a.x, acc);
        acc = fmaf(w.y, a.y, acc);
        acc = fmaf(w.z, a.z, acc);
        acc = fmaf(w.w, a.w, acc);
    }
    acc = warpSum(acc);
    if (lane == 0) g_w2[k] = acc;
}

// K2: s2[r] = dot(X[r,:], w2). 1024 blocks x 256 threads, warp per row.
__global__ __launch_bounds__(256) void k2_s2(const float* __restrict__ X) {
    __shared__ float w2s[DIM];
    const int t = threadIdx.x;
    #pragma unroll
    for (int j = t; j < DIM; j += 256) w2s[j] = g_w2[j];
    __syncthreads();

    const int warp = t >> 5, lane = t & 31;
    const int r = blockIdx.x * 8 + warp;
    const float4* X4 = (const float4*)X;
    const float4* W4 = (const float4*)w2s;
    float acc = 0.f;
    #pragma unroll
    for (int j = lane; j < 128; j += 32) {
        float4 x = X4[r * 128 + j];
        float4 w = W4[j];
        acc = fmaf(x.x, w.x, acc);
        acc = fmaf(x.y, w.y, acc);
        acc = fmaf(x.z, w.z, acc);
        acc = fmaf(x.w, w.w, acc);
    }
    acc = warpSum(acc);
    if (lane == 0) g_s2[r] = acc;
}

// K4: fused softmax + u partials. 256 blocks x 256 threads, 32 rows/block.
// Every block redundantly computes the global softmax max/sum (deterministic,
// identical across blocks), then its own 32 p-values, then the weighted
// column sums for its rows. Partials -> g_up[256][512].
__global__ __launch_bounds__(256) void k4_fused(const float* __restrict__ X) {
    __shared__ float sm[8];
    __shared__ float bc[2];
    __shared__ float p_s[32];
    const int t = threadIdx.x, warp = t >> 5, lane = t & 31;

    // global max over s2
    const float4* s4 = (const float4*)g_s2;
    float4 v[8];
    float m = -INFINITY;
    #pragma unroll
    for (int j = 0; j < 8; j++) {
        v[j] = s4[t + 256 * j];
        m = fmaxf(m, fmaxf(fmaxf(v[j].x, v[j].y), fmaxf(v[j].z, v[j].w)));
    }
    m = warpMax(m);
    if (lane == 0) sm[warp] = m;
    __syncthreads();
    if (warp == 0) {
        float x = (lane < 8) ? sm[lane] : -INFINITY;
        x = warpMax(x);
        if (lane == 0) bc[0] = x;
    }
    __syncthreads();
    const float mx = bc[0];

    // global sum of exp
    float ls = 0.f;
    #pragma unroll
    for (int j = 0; j < 8; j++) {
        ls += __expf(v[j].x - mx) + __expf(v[j].y - mx)
            + __expf(v[j].z - mx) + __expf(v[j].w - mx);
    }
    ls = warpSum(ls);
    if (lane == 0) sm[warp] = ls;
    __syncthreads();
    if (warp == 0) {
        float x = (lane < 8) ? sm[lane] : 0.f;
        x = warpSum(x);
        if (lane == 0) bc[1] = 1.f / x;
    }
    __syncthreads();
    const float inv = bc[1];

    // this block's 32 p-values
    const int r0 = blockIdx.x * 32;
    if (t < 32) p_s[t] = __expf(g_s2[r0 + t] - mx) * inv;
    __syncthreads();

    // weighted column sums: thread t owns cols t and t+256
    float a0 = 0.f, a1 = 0.f;
    #pragma unroll 8
    for (int i = 0; i < 32; i++) {
        const float pi = p_s[i];
        const float* xr = X + (size_t)(r0 + i) * DIM;
        a0 = fmaf(pi, xr[t], a0);
        a1 = fmaf(pi, xr[t + 256], a1);
    }
    g_up[blockIdx.x * DIM + t]       = a0;
    g_up[blockIdx.x * DIM + t + 256] = a1;
}

// K5: u-reduce + v = u @ W. 8 blocks x 256 threads.
// Phase A: each thread reduces 2 columns of g_up (256 partials each) into smem u.
// Phase B: split-k GEMV; block j computes v[j*64 .. j*64+63].
__global__ __launch_bounds__(256) void k5_v(const float* __restrict__ W) {
    __shared__ float us[DIM];
    __shared__ float pb[256];
    const int t = threadIdx.x;

    float a0 = 0.f, a1 = 0.f;
    #pragma unroll 8
    for (int b = 0; b < 256; b++) {
        a0 += g_up[b * DIM + t];
        a1 += g_up[b * DIM + t + 256];
    }
    us[t] = a0;
    us[t + 256] = a1;
    __syncthreads();

    const int c = blockIdx.x * 64 + (t & 63);   // output column
    const int g = t >> 6;                       // k-group 0..3
    float acc0 = 0.f, acc1 = 0.f;
    const int k0 = g * 128;
    #pragma unroll 4
    for (int k = 0; k < 128; k += 2) {
        acc0 = fmaf(us[k0 + k],     W[(size_t)(k0 + k) * DIM + c],     acc0);
        acc1 = fmaf(us[k0 + k + 1], W[(size_t)(k0 + k + 1) * DIM + c], acc1);
    }
    pb[t] = acc0 + acc1;
    __syncthreads();
    if (t < 64)
        g_v[blockIdx.x * 64 + t] = (pb[t] + pb[t + 64]) + (pb[t + 128] + pb[t + 192]);
}

// K6: broadcast v into every output row. 1024 blocks x 256 threads,
// 4 float4 stores per thread (8 rows per block).
__global__ __launch_bounds__(256) void k6_broadcast(float4* __restrict__ out4) {
    const float4* v4 = (const float4*)g_v;
    const unsigned base = blockIdx.x * 1024u + threadIdx.x * 4u;
    #pragma unroll
    for (int i = 0; i < 4; i++)
        out4[base + i] = v4[(threadIdx.x * 4 + i) & 127u];
}

extern "C" void kernel_launch(void* const* d_in, const int* in_sizes, int n_in,
                              void* d_out, int out_size) {
    const float* X  = (const float*)d_in[0];   // node_features [8192,512]
    const float* W  = (const float*)d_in[1];   // weight_matrix [512,512]
    const float* av = (const float*)d_in[2];   // attention_vector [1024,1]
    float* out = (float*)d_out;                // [8192,512]

    k1_w2<<<64, 256>>>(W, av);
    k2_s2<<<NROWS / 8, 256>>>(X);
    k4_fused<<<256, 256>>>(X);
    k5_v<<<8, 256>>>(W);
    k6_broadcast<<<1024, 256>>>((float4*)out);
}

// round 4
// speedup vs baseline: 1.5033x; 1.4161x over previous
#include <cuda_runtime.h>
#include <math.h>

#define NROWS 8192
#define DIM   512

// Scratch (device globals — no allocation allowed)
__device__ float g_w2[DIM];         // w2 = W @ a2
__device__ float g_s2[NROWS];       // s2 = X @ w2
__device__ float g_up[256 * DIM];   // partial u = p @ X over 256 row-chunks
__device__ float g_u[DIM];          // u = p @ X
__device__ float g_vp[8 * DIM];     // split-k partials of v = u @ W
__device__ float g_pad[32];         // guard

__device__ __forceinline__ float warpMax(float v) {
    #pragma unroll
    for (int o = 16; o; o >>= 1) v = fmaxf(v, __shfl_xor_sync(0xffffffffu, v, o));
    return v;
}
__device__ __forceinline__ float warpSum(float v) {
    #pragma unroll
    for (int o = 16; o; o >>= 1) v += __shfl_xor_sync(0xffffffffu, v, o);
    return v;
}

// K1: w2[k] = dot(W[k,:], a2).  64 blocks x 256 threads, warp per row.
__global__ __launch_bounds__(256) void k1_w2(const float* __restrict__ W,
                                             const float* __restrict__ av) {
    const int warp = threadIdx.x >> 5, lane = threadIdx.x & 31;
    const int k = blockIdx.x * 8 + warp;
    const float4* Wr = (const float4*)(W + (size_t)k * DIM);
    const float4* A2 = (const float4*)(av + DIM);    // a2 = av[512:1024]
    float acc = 0.f;
    #pragma unroll
    for (int j = lane; j < 128; j += 32) {
        float4 w = Wr[j];
        float4 a = A2[j];
        acc = fmaf(w.x, a.x, acc);
        acc = fmaf(w.y, a.y, acc);
        acc = fmaf(w.z, a.z, acc);
        acc = fmaf(w.w, a.w, acc);
    }
    acc = warpSum(acc);
    if (lane == 0) g_w2[k] = acc;
}

// K2: s2[r] = dot(X[r,:], w2). 1024 blocks x 256 threads, warp per row.
__global__ __launch_bounds__(256) void k2_s2(const float* __restrict__ X) {
    __shared__ float w2s[DIM];
    const int t = threadIdx.x;
    #pragma unroll
    for (int j = t; j < DIM; j += 256) w2s[j] = g_w2[j];
    __syncthreads();

    const int warp = t >> 5, lane = t & 31;
    const int r = blockIdx.x * 8 + warp;
    const float4* X4 = (const float4*)X;
    const float4* W4 = (const float4*)w2s;
    float acc = 0.f;
    #pragma unroll
    for (int j = lane; j < 128; j += 32) {
        float4 x = X4[r * 128 + j];
        float4 w = W4[j];
        acc = fmaf(x.x, w.x, acc);
        acc = fmaf(x.y, w.y, acc);
        acc = fmaf(x.z, w.z, acc);
        acc = fmaf(x.w, w.w, acc);
    }
    acc = warpSum(acc);
    if (lane == 0) g_s2[r] = acc;
}

// K4: fused softmax + u partials. 256 blocks x 256 threads, 32 rows/block.
// Every block redundantly computes the global softmax max/sum (deterministic,
// identical across blocks), then its own 32 p-values, then the weighted
// column sums for its rows. Partials -> g_up[256][512].
__global__ __launch_bounds__(256) void k4_fused(const float* __restrict__ X) {
    __shared__ float sm[8];
    __shared__ float bc[2];
    __shared__ float p_s[32];
    const int t = threadIdx.x, warp = t >> 5, lane = t & 31;

    // global max over s2
    const float4* s4 = (const float4*)g_s2;
    float4 v[8];
    float m = -INFINITY;
    #pragma unroll
    for (int j = 0; j < 8; j++) {
        v[j] = s4[t + 256 * j];
        m = fmaxf(m, fmaxf(fmaxf(v[j].x, v[j].y), fmaxf(v[j].z, v[j].w)));
    }
    m = warpMax(m);
    if (lane == 0) sm[warp] = m;
    __syncthreads();
    if (warp == 0) {
        float x = (lane < 8) ? sm[lane] : -INFINITY;
        x = warpMax(x);
        if (lane == 0) bc[0] = x;
    }
    __syncthreads();
    const float mx = bc[0];

    // global sum of exp
    float ls = 0.f;
    #pragma unroll
    for (int j = 0; j < 8; j++) {
        ls += __expf(v[j].x - mx) + __expf(v[j].y - mx)
            + __expf(v[j].z - mx) + __expf(v[j].w - mx);
    }
    ls = warpSum(ls);
    if (lane == 0) sm[warp] = ls;
    __syncthreads();
    if (warp == 0) {
        float x = (lane < 8) ? sm[lane] : 0.f;
        x = warpSum(x);
        if (lane == 0) bc[1] = 1.f / x;
    }
    __syncthreads();
    const float inv = bc[1];

    // this block's 32 p-values
    const int r0 = blockIdx.x * 32;
    if (t < 32) p_s[t] = __expf(g_s2[r0 + t] - mx) * inv;
    __syncthreads();

    // weighted column sums: thread t owns cols t and t+256
    float a0 = 0.f, a1 = 0.f;
    #pragma unroll 8
    for (int i = 0; i < 32; i++) {
        const float pi = p_s[i];
        const float* xr = X + (size_t)(r0 + i) * DIM;
        a0 = fmaf(pi, xr[t], a0);
        a1 = fmaf(pi, xr[t + 256], a1);
    }
    g_up[blockIdx.x * DIM + t]       = a0;
    g_up[blockIdx.x * DIM + t + 256] = a1;
}

// K5a: reduce 256 u-partials per column. 64 blocks x 256 threads,
// warp per column; lane reduces 8 strided partials, then shuffle-reduce.
__global__ __launch_bounds__(256) void k5a_u(void) {
    const int warp = threadIdx.x >> 5, lane = threadIdx.x & 31;
    const int col = blockIdx.x * 8 + warp;      // 0..511
    float acc = 0.f;
    #pragma unroll
    for (int i = 0; i < 8; i++)
        acc += g_up[(size_t)(lane + 32 * i) * DIM + col];
    acc = warpSum(acc);
    if (lane == 0) g_u[col] = acc;
}

// K5b: split-k partial GEMV. grid (8 kc, 8 cc) x 256 threads.
// Block (kc,cc): cols cc*64..+63, k-rows kc*64..+63. Each W element read once.
__global__ __launch_bounds__(256) void k5b_v(const float* __restrict__ W) {
    __shared__ float us[64];
    __shared__ float pb[256];
    const int t = threadIdx.x;
    const int kc = blockIdx.x, cc = blockIdx.y;
    if (t < 64) us[t] = g_u[kc * 64 + t];
    __syncthreads();

    const int cl = t & 63;                 // local col
    const int ks = t >> 6;                 // k-subgroup 0..3 (16 k's each)
    const int col = cc * 64 + cl;
    const int k0 = kc * 64 + ks * 16;
    float a0 = 0.f, a1 = 0.f;
    #pragma unroll
    for (int i = 0; i < 16; i += 2) {
        a0 = fmaf(us[ks * 16 + i],     W[(size_t)(k0 + i) * DIM + col],     a0);
        a1 = fmaf(us[ks * 16 + i + 1], W[(size_t)(k0 + i + 1) * DIM + col], a1);
    }
    pb[t] = a0 + a1;
    __syncthreads();
    if (t < 64)
        g_vp[kc * DIM + col] = (pb[cl] + pb[cl + 64]) + (pb[cl + 128] + pb[cl + 192]);
}

// K6: reduce 8 v-partials + broadcast into all 8192 rows.
// 1024 blocks x 256 threads; each block stores 8 rows (4 float4/thread).
__global__ __launch_bounds__(256) void k6_bcast(float4* __restrict__ out4) {
    __shared__ float vs[DIM];
    const int t = threadIdx.x;
    #pragma unroll
    for (int c = t; c < DIM; c += 256) {
        float a = 0.f;
        #pragma unroll
        for (int j = 0; j < 8; j++) a += g_vp[j * DIM + c];
        vs[c] = a;
    }
    __syncthreads();
    const float4* v4 = (const float4*)vs;
    const unsigned base = blockIdx.x * 1024u + t * 4u;
    #pragma unroll
    for (int i = 0; i < 4; i++)
        out4[base + i] = v4[(t * 4 + i) & 127u];
}

extern "C" void kernel_launch(void* const* d_in, const int* in_sizes, int n_in,
                              void* d_out, int out_size) {
    const float* X  = (const float*)d_in[0];   // node_features [8192,512]
    const float* W  = (const float*)d_in[1];   // weight_matrix [512,512]
    const float* av = (const float*)d_in[2];   // attention_vector [1024,1]
    float* out = (float*)d_out;                // [8192,512]

    k1_w2<<<64, 256>>>(W, av);
    k2_s2<<<NROWS / 8, 256>>>(X);
    k4_fused<<<256, 256>>>(X);
    k5a_u<<<64, 256>>>();
    k5b_v<<<dim3(8, 8), 256>>>(W);
    k6_bcast<<<1024, 256>>>((float4*)out);
}

// round 6
// speedup vs baseline: 1.5091x; 1.0039x over previous
#include <cuda_runtime.h>
#include <math.h>

#define NROWS 8192
#define DIM   512

// Scratch (device globals — no allocation allowed)
__device__ float g_w2[DIM];         // w2 = W @ a2
__device__ float g_s2[NROWS];       // s2 = X @ w2
__device__ float g_up[256 * DIM];   // partial u = p @ X over 256 row-chunks
__device__ float g_vp[8 * DIM];     // split-k partials of v = u @ W

__device__ __forceinline__ float warpMax(float v) {
    #pragma unroll
    for (int o = 16; o; o >>= 1) v = fmaxf(v, __shfl_xor_sync(0xffffffffu, v, o));
    return v;
}
__device__ __forceinline__ float warpSum(float v) {
    #pragma unroll
    for (int o = 16; o; o >>= 1) v += __shfl_xor_sync(0xffffffffu, v, o);
    return v;
}

// K1: w2[k] = dot(W[k,:], a2).  64 blocks x 256 threads, warp per row.
__global__ __launch_bounds__(256) void k1_w2(const float* __restrict__ W,
                                             const float* __restrict__ av) {
    const int warp = threadIdx.x >> 5, lane = threadIdx.x & 31;
    const int k = blockIdx.x * 8 + warp;
    const float4* Wr = (const float4*)(W + (size_t)k * DIM);
    const float4* A2 = (const float4*)(av + DIM);    // a2 = av[512:1024]
    float acc = 0.f;
    #pragma unroll
    for (int j = lane; j < 128; j += 32) {
        float4 w = Wr[j];
        float4 a = A2[j];
        acc = fmaf(w.x, a.x, acc);
        acc = fmaf(w.y, a.y, acc);
        acc = fmaf(w.z, a.z, acc);
        acc = fmaf(w.w, a.w, acc);
    }
    acc = warpSum(acc);
    if (lane == 0) g_w2[k] = acc;
}

// K2: s2[r] = dot(X[r,:], w2). 1024 blocks x 256 threads, warp per row.
__global__ __launch_bounds__(256) void k2_s2(const float* __restrict__ X) {
    __shared__ float w2s[DIM];
    const int t = threadIdx.x;
    #pragma unroll
    for (int j = t; j < DIM; j += 256) w2s[j] = g_w2[j];
    __syncthreads();

    const int warp = t >> 5, lane = t & 31;
    const int r = blockIdx.x * 8 + warp;
    const float4* X4 = (const float4*)X;
    const float4* W4 = (const float4*)w2s;
    float acc = 0.f;
    #pragma unroll
    for (int j = lane; j < 128; j += 32) {
        float4 x = X4[r * 128 + j];
        float4 w = W4[j];
        acc = fmaf(x.x, w.x, acc);
        acc = fmaf(x.y, w.y, acc);
        acc = fmaf(x.z, w.z, acc);
        acc = fmaf(x.w, w.w, acc);
    }
    acc = warpSum(acc);
    if (lane == 0) g_s2[r] = acc;
}

// K4: fused softmax + u partials. 256 blocks x 256 threads, 32 rows/block.
// Every block redundantly computes the global softmax max/sum (deterministic,
// identical across blocks), then its own 32 p-values, then the weighted
// column sums for its rows. Partials -> g_up[256][512].
__global__ __launch_bounds__(256) void k4_fused(const float* __restrict__ X) {
    __shared__ float sm[8];
    __shared__ float bc[2];
    __shared__ float p_s[32];
    const int t = threadIdx.x, warp = t >> 5, lane = t & 31;

    // global max over s2
    const float4* s4 = (const float4*)g_s2;
    float4 v[8];
    float m = -INFINITY;
    #pragma unroll
    for (int j = 0; j < 8; j++) {
        v[j] = s4[t + 256 * j];
        m = fmaxf(m, fmaxf(fmaxf(v[j].x, v[j].y), fmaxf(v[j].z, v[j].w)));
    }
    m = warpMax(m);
    if (lane == 0) sm[warp] = m;
    __syncthreads();
    if (warp == 0) {
        float x = (lane < 8) ? sm[lane] : -INFINITY;
        x = warpMax(x);
        if (lane == 0) bc[0] = x;
    }
    __syncthreads();
    const float mx = bc[0];

    // global sum of exp
    float ls = 0.f;
    #pragma unroll
    for (int j = 0; j < 8; j++) {
        ls += __expf(v[j].x - mx) + __expf(v[j].y - mx)
            + __expf(v[j].z - mx) + __expf(v[j].w - mx);
    }
    ls = warpSum(ls);
    if (lane == 0) sm[warp] = ls;
    __syncthreads();
    if (warp == 0) {
        float x = (lane < 8) ? sm[lane] : 0.f;
        x = warpSum(x);
        if (lane == 0) bc[1] = 1.f / x;
    }
    __syncthreads();
    const float inv = bc[1];

    // this block's 32 p-values
    const int r0 = blockIdx.x * 32;
    if (t < 32) p_s[t] = __expf(g_s2[r0 + t] - mx) * inv;
    __syncthreads();

    // weighted column sums: thread t owns cols t and t+256
    float a0 = 0.f, a1 = 0.f;
    #pragma unroll 8
    for (int i = 0; i < 32; i++) {
        const float pi = p_s[i];
        const float* xr = X + (size_t)(r0 + i) * DIM;
        a0 = fmaf(pi, xr[t], a0);
        a1 = fmaf(pi, xr[t + 256], a1);
    }
    g_up[blockIdx.x * DIM + t]       = a0;
    g_up[blockIdx.x * DIM + t + 256] = a1;
}

// K5: fused u-reduce + split-k GEMV. grid (8 kc, 8 cc) x 256 threads.
// Phase A: block reduces the 256 u-partials for its own 64-column k-chunk,
// threads laid ACROSS columns (coalesced; 64 independent loads per thread).
// Phase B: v-partial for cols cc*64..+63 over k-rows kc*64..+63.
__global__ __launch_bounds__(256) void k5_v(const float* __restrict__ W) {
    __shared__ float us[64];
    __shared__ float pb[256];
    const int t = threadIdx.x;
    const int kc = blockIdx.x, cc = blockIdx.y;
    const int cl = t & 63;                 // local col 0..63
    const int g  = t >> 6;                 // partial-group 0..3

    // Phase A: u[kc*64 + cl] = sum over 256 partial rows
    {
        const size_t base = (size_t)(g * 64) * DIM + kc * 64 + cl;
        float a0 = 0.f, a1 = 0.f, a2 = 0.f, a3 = 0.f;
        #pragma unroll
        for (int r = 0; r < 64; r += 4) {
            a0 += g_up[base + (size_t)(r + 0) * DIM];
            a1 += g_up[base + (size_t)(r + 1) * DIM];
            a2 += g_up[base + (size_t)(r + 2) * DIM];
            a3 += g_up[base + (size_t)(r + 3) * DIM];
        }
        pb[t] = (a0 + a1) + (a2 + a3);
    }
    __syncthreads();
    if (t < 64) us[t] = (pb[t] + pb[t + 64]) + (pb[t + 128] + pb[t + 192]);
    __syncthreads();

    // Phase B: GEMV partial. thread t: col cc*64+cl, k's kc*64+g*16..+15
    const int col = cc * 64 + cl;
    const int k0 = kc * 64 + g * 16;
    float a0 = 0.f, a1 = 0.f;
    #pragma unroll
    for (int i = 0; i < 16; i += 2) {
        a0 = fmaf(us[g * 16 + i],     W[(size_t)(k0 + i) * DIM + col],     a0);
        a1 = fmaf(us[g * 16 + i + 1], W[(size_t)(k0 + i + 1) * DIM + col], a1);
    }
    pb[t] = a0 + a1;
    __syncthreads();
    if (t < 64)
        g_vp[kc * DIM + col] = (pb[cl] + pb[cl + 64]) + (pb[cl + 128] + pb[cl + 192]);
}

// K6: reduce 8 v-partials + broadcast into all 8192 rows.
// 1024 blocks x 256 threads; each block stores 8 rows (4 float4/thread).
__global__ __launch_bounds__(256) void k6_bcast(float4* __restrict__ out4) {
    __shared__ float vs[DIM];
    const int t = threadIdx.x;
    #pragma unroll
    for (int c = t; c < DIM; c += 256) {
        float a = 0.f;
        #pragma unroll
        for (int j = 0; j < 8; j++) a += g_vp[j * DIM + c];
        vs[c] = a;
    }
    __syncthreads();
    const float4* v4 = (const float4*)vs;
    const unsigned base = blockIdx.x * 1024u + t * 4u;
    #pragma unroll
    for (int i = 0; i < 4; i++)
        out4[base + i] = v4[(t * 4 + i) & 127u];
}

extern "C" void kernel_launch(void* const* d_in, const int* in_sizes, int n_in,
                              void* d_out, int out_size) {
    const float* X  = (const float*)d_in[0];   // node_features [8192,512]
    const float* W  = (const float*)d_in[1];   // weight_matrix [512,512]
    const float* av = (const float*)d_in[2];   // attention_vector [1024,1]
    float* out = (float*)d_out;                // [8192,512]

    k1_w2<<<64, 256>>>(W, av);
    k2_s2<<<NROWS / 8, 256>>>(X);
    k4_fused<<<256, 256>>>(X);
    k5_v<<<dim3(8, 8), 256>>>(W);
    k6_bcast<<<1024, 256>>>((float4*)out);
}